// round 14
// baseline (speedup 1.0000x reference)
#include <cuda_runtime.h>
#include <cuda_bf16.h>

#define GSZ   32
#define NCTRL 68

typedef unsigned long long u64;

__device__ __forceinline__ u64 f2pack(float lo, float hi) {
    u64 r; asm("mov.b64 %0,{%1,%2};" : "=l"(r) : "f"(lo), "f"(hi)); return r;
}
__device__ __forceinline__ void f2unpack(u64 v, float& lo, float& hi) {
    asm("mov.b64 {%0,%1},%2;" : "=f"(lo), "=f"(hi) : "l"(v));
}
__device__ __forceinline__ float frcp(float x) {
    float r; asm("rcp.approx.f32 %0,%1;" : "=f"(r) : "f"(x)); return r;
}

// Block 1: integer/table path (ALU + LSU pipes only, no fma-pipe ops).
// Produces the four per-pixel weights w = 1/(d^2+1e-8) as two f32x2 pairs,
// via table lookups:  addr = wdup_base + 16*d2 + 4*(lane&3)
//   sqx[t]  = wdup_base + 16*(t-31)^2           (t = kxi - col + 31; lane-linear
//                                                addresses -> conflict-free)
//   sqyv[4t+j] = 16*(t-31-4j)^2                 (t = kyi - r0 + 31; warp-uniform
//                                                -> one broadcast v4 load)
__device__ __forceinline__ void mls_weights(
    u64& wA, u64& wB, unsigned s, unsigned Bx, unsigned By, unsigned LO)
{
    asm("{\n\t"
        ".reg .u32 kxi, kyi, t0, t1, ax, ay, sx, a0, a1, a2, a3;\n\t"
        ".reg .b32 sy0, sy1, sy2, sy3, w0, w1, w2, w3;\n\t"
        "ld.shared.v2.u32 {kxi, kyi}, [%2+32];\n\t"
        "shl.b32 t0, kxi, 2;\n\t"
        "add.s32 ax, %3, t0;\n\t"
        "shl.b32 t1, kyi, 4;\n\t"
        "add.s32 ay, %4, t1;\n\t"
        "ld.shared.u32 sx, [ax];\n\t"
        "ld.shared.v4.b32 {sy0, sy1, sy2, sy3}, [ay];\n\t"
        "add.s32 sx, sx, %5;\n\t"
        "add.s32 a0, sx, sy0;\n\t"
        "add.s32 a1, sx, sy1;\n\t"
        "add.s32 a2, sx, sy2;\n\t"
        "add.s32 a3, sx, sy3;\n\t"
        "ld.shared.b32 w0, [a0];\n\t"
        "ld.shared.b32 w1, [a1];\n\t"
        "ld.shared.b32 w2, [a2];\n\t"
        "ld.shared.b32 w3, [a3];\n\t"
        "mov.b64 %0, {w0, w1};\n\t"
        "mov.b64 %1, {w2, w3};\n\t"
        "}"
        : "=l"(wA), "=l"(wB)
        : "r"(s), "r"(Bx), "r"(By), "r"(LO));
}

// Block 2: pure f32x2 math (31 fma-pipe ops): dx, dyA, dyB(=dyA-8), 4 muls,
// 24 accumulates. dyB = dyA - 8 is exact (small integers in fp32).
__device__ __forceinline__ void mls_accum(
    u64& swA, u64& SxA, u64& SyA, u64& SxxA, u64& SxyA, u64& SyyA,
    u64& SqxA, u64& SqyA, u64& S1A, u64& S2A, u64& S3A, u64& S4A,
    u64& swB, u64& SxB, u64& SyB, u64& SxxB, u64& SxyB, u64& SyyB,
    u64& SqxB, u64& SqyB, u64& S1B, u64& S2B, u64& S3B, u64& S4B,
    u64 wA, u64 wB, unsigned s, u64 nvx2, u64 nvyA2, u64 m8)
{
    asm("{\n\t"
        ".reg .b64 kx2, ky2, qx2, qy2, dx, dyA, dyB;\n\t"
        ".reg .b64 wdxA, wdyA, wdxB, wdyB;\n\t"
        "ld.shared.v2.b64 {kx2, ky2}, [%26];\n\t"
        "ld.shared.v2.b64 {qx2, qy2}, [%26+16];\n\t"
        "add.rn.f32x2 dx, kx2, %27;\n\t"
        "add.rn.f32x2 dyA, ky2, %28;\n\t"
        "add.rn.f32x2 dyB, dyA, %29;\n\t"
        "mul.rn.f32x2 wdxA, %24, dx;\n\t"
        "mul.rn.f32x2 wdyA, %24, dyA;\n\t"
        "mul.rn.f32x2 wdxB, %25, dx;\n\t"
        "mul.rn.f32x2 wdyB, %25, dyB;\n\t"
        // set A accumulators
        "add.rn.f32x2 %0, %0, %24;\n\t"
        "add.rn.f32x2 %1, %1, wdxA;\n\t"
        "add.rn.f32x2 %2, %2, wdyA;\n\t"
        "fma.rn.f32x2 %3, wdxA, dx, %3;\n\t"
        "fma.rn.f32x2 %4, wdxA, dyA, %4;\n\t"
        "fma.rn.f32x2 %5, wdyA, dyA, %5;\n\t"
        "fma.rn.f32x2 %6, %24, qx2, %6;\n\t"
        "fma.rn.f32x2 %7, %24, qy2, %7;\n\t"
        "fma.rn.f32x2 %8, wdxA, qx2, %8;\n\t"
        "fma.rn.f32x2 %9, wdyA, qx2, %9;\n\t"
        "fma.rn.f32x2 %10, wdxA, qy2, %10;\n\t"
        "fma.rn.f32x2 %11, wdyA, qy2, %11;\n\t"
        // set B accumulators
        "add.rn.f32x2 %12, %12, %25;\n\t"
        "add.rn.f32x2 %13, %13, wdxB;\n\t"
        "add.rn.f32x2 %14, %14, wdyB;\n\t"
        "fma.rn.f32x2 %15, wdxB, dx, %15;\n\t"
        "fma.rn.f32x2 %16, wdxB, dyB, %16;\n\t"
        "fma.rn.f32x2 %17, wdyB, dyB, %17;\n\t"
        "fma.rn.f32x2 %18, %25, qx2, %18;\n\t"
        "fma.rn.f32x2 %19, %25, qy2, %19;\n\t"
        "fma.rn.f32x2 %20, wdxB, qx2, %20;\n\t"
        "fma.rn.f32x2 %21, wdyB, qx2, %21;\n\t"
        "fma.rn.f32x2 %22, wdxB, qy2, %22;\n\t"
        "fma.rn.f32x2 %23, wdyB, qy2, %23;\n\t"
        "}"
        : "+l"(swA), "+l"(SxA), "+l"(SyA), "+l"(SxxA), "+l"(SxyA), "+l"(SyyA),
          "+l"(SqxA), "+l"(SqyA), "+l"(S1A), "+l"(S2A), "+l"(S3A), "+l"(S4A),
          "+l"(swB), "+l"(SxB), "+l"(SyB), "+l"(SxxB), "+l"(SxyB), "+l"(SyyB),
          "+l"(SqxB), "+l"(SqyB), "+l"(S1B), "+l"(S2B), "+l"(S3B), "+l"(S4B)
        : "l"(wA), "l"(wB), "r"(s), "l"(nvx2), "l"(nvyA2), "l"(m8));
}

// Scalar epilogue: closed-form 2x2 solve from raw weighted moments.
__device__ __forceinline__ void mls_finish(
    float sw, float sx, float sy,
    float sxx, float sxy, float syy,
    float sqx, float sqy,
    float sdxqx, float sdyqx, float sdxqy, float sdyqy,
    float* __restrict__ ob, int pix)
{
    const float isw = frcp(sw);
    const float mx  = sx * isw,  my  = sy * isw;
    const float a11 = fmaf(sxx, isw, -(mx * mx));
    const float a12 = fmaf(sxy, isw, -(mx * my));
    const float a22 = fmaf(syy, isw, -(my * my));
    const float qsx = sqx * isw, qsy = sqy * isw;
    const float bxx = fmaf(sdxqx, isw, -(mx * qsx));
    const float bxy = fmaf(sdyqx, isw, -(my * qsx));
    const float byx = fmaf(sdxqy, isw, -(mx * qsy));
    const float byy = fmaf(sdyqy, isw, -(my * qsy));

    const float det  = fmaf(a11, a22, -(a12 * a12));
    const float idet = frcp(det);
    const float ux = -mx, uy = -my;
    const float rx = (ux * a22 - uy * a12) * idet;
    const float ry = (uy * a11 - ux * a12) * idet;

    float tx = fmaf(rx, bxx, fmaf(ry, bxy, qsx));
    float ty = fmaf(rx, byx, fmaf(ry, byy, qsy));

    if (!(tx >= 0.f) || tx > (float)(GSZ - 1)) tx = 0.f;
    if (!(ty >= 0.f) || ty > (float)(GSZ - 1)) ty = 0.f;

    ob[pix]             = tx;   // channel 0 (x)
    ob[GSZ * GSZ + pix] = ty;   // channel 1 (y)
}

// 128 threads per CTA, each handles 4 pixels in one column: rows r0, r0+4,
// r0+8, r0+12 of a 16-row band. grid = (2, B).
__global__ __launch_bounds__(128)
void mls_warp_kernel(const float* __restrict__ sp,
                     const float* __restrict__ dp,
                     float* __restrict__ out)
{
    // Per control, 48B: kx2(8) ky2(8) qx2(8) qy2(8) kxi(4) kyi(4) pad(8)
    __shared__ __align__(16) u64 cs[NCTRL * 6];
    __shared__ __align__(16) unsigned sqx[63];         // wb + 16*(t-31)^2
    __shared__ __align__(16) unsigned sqyv[63 * 4];    // 16*(t-31-4j)^2
    __shared__ __align__(16) float    wdup[1923 * 4];  // w[d2] x4 lane-dither

    const int b    = blockIdx.y;
    const int band = blockIdx.x;
    const int tid  = threadIdx.x;

    const unsigned wb = (unsigned)__cvta_generic_to_shared(wdup);

    if (tid < NCTRL) {
        const float* spb = sp + (size_t)b * (NCTRL * 2) + tid * 2;
        const float* dpb = dp + (size_t)b * (NCTRL * 2) + tid * 2;
        // coord swap + int16 truncation, exactly as the reference
        int   kxi = (int)(short)dpb[1];
        int   kyi = (int)(short)dpb[0];
        float kx = (float)kxi, ky = (float)kyi;
        float qx = (float)(short)spb[1];
        float qy = (float)(short)spb[0];
        cs[tid * 6 + 0] = f2pack(kx, kx);
        cs[tid * 6 + 1] = f2pack(ky, ky);
        cs[tid * 6 + 2] = f2pack(qx, qx);
        cs[tid * 6 + 3] = f2pack(qy, qy);
        ((int*)&cs[tid * 6 + 4])[0] = kxi;
        ((int*)&cs[tid * 6 + 4])[1] = kyi;
    }
    // sqx: x-distance squares, base-folded into w-table address
    for (int t = tid; t < 63; t += 128) {
        int d = t - 31;
        sqx[t] = wb + 16u * (unsigned)(d * d);
    }
    // sqyv: y-distance squares for the thread's 4 rows, interleaved for v4 load
    for (int i = tid; i < 63 * 4; i += 128) {
        int t = i >> 2, j = i & 3;
        int d = t - 31 - 4 * j;
        sqyv[i] = 16u * (unsigned)(d * d);
    }
    // w table: exact reference weights. d2>=1: 1e-8 is below 1/2 ulp -> 1/d2.
    for (int i = tid; i < 1923; i += 128) {
        float w = (i == 0) ? (1.0f / 1e-8f) : __frcp_rn((float)i);
        ((float4*)wdup)[i] = make_float4(w, w, w, w);
    }
    __syncthreads();

    const int pix0 = band * 512 + tid;         // pixels at pix0 + {0,128,256,384}
    const int col  = tid & 31;
    const int r0   = band * 16 + (tid >> 5);
    const float vx = (float)col;
    const float fr0 = (float)r0;

    const u64 nvx2  = f2pack(-vx, -vx);
    const u64 nvyA2 = f2pack(-fr0, -(fr0 + 4.0f));   // rows r0, r0+4
    const u64 m8    = f2pack(-8.0f, -8.0f);          // dyB = dyA - 8

    const unsigned Bx = (unsigned)__cvta_generic_to_shared(sqx) + 124u - 4u * (unsigned)col;
    const unsigned By = (unsigned)__cvta_generic_to_shared(sqyv) + 496u - 16u * (unsigned)r0;
    const unsigned LO = ((unsigned)tid & 3u) << 2;

    u64 swA = 0, SxA = 0, SyA = 0, SxxA = 0, SxyA = 0, SyyA = 0;
    u64 SqxA = 0, SqyA = 0, S1A = 0, S2A = 0, S3A = 0, S4A = 0;
    u64 swB = 0, SxB = 0, SyB = 0, SxxB = 0, SxyB = 0, SyyB = 0;
    u64 SqxB = 0, SqyB = 0, S1B = 0, S2B = 0, S3B = 0, S4B = 0;

    unsigned s = (unsigned)__cvta_generic_to_shared(cs);
#pragma unroll 2
    for (int c = 0; c < NCTRL; ++c, s += 48u) {
        u64 wA, wB;
        mls_weights(wA, wB, s, Bx, By, LO);
        mls_accum(swA, SxA, SyA, SxxA, SxyA, SyyA, SqxA, SqyA, S1A, S2A, S3A, S4A,
                  swB, SxB, SyB, SxxB, SxyB, SyyB, SqxB, SqyB, S1B, S2B, S3B, S4B,
                  wA, wB, s, nvx2, nvyA2, m8);
    }

    float* ob = out + (size_t)b * (2 * GSZ * GSZ);

    {   // set A -> pixels pix0, pix0+128
        float swl, swh, sxl, sxh, syl, syh, sxxl, sxxh, sxyl, sxyh, syyl, syyh;
        float sqxl, sqxh, sqyl, sqyh, s1l, s1h, s2l, s2h, s3l, s3h, s4l, s4h;
        f2unpack(swA, swl, swh);   f2unpack(SxA, sxl, sxh);   f2unpack(SyA, syl, syh);
        f2unpack(SxxA, sxxl, sxxh); f2unpack(SxyA, sxyl, sxyh); f2unpack(SyyA, syyl, syyh);
        f2unpack(SqxA, sqxl, sqxh); f2unpack(SqyA, sqyl, sqyh);
        f2unpack(S1A, s1l, s1h); f2unpack(S2A, s2l, s2h);
        f2unpack(S3A, s3l, s3h); f2unpack(S4A, s4l, s4h);
        mls_finish(swl, sxl, syl, sxxl, sxyl, syyl, sqxl, sqyl, s1l, s2l, s3l, s4l, ob, pix0);
        mls_finish(swh, sxh, syh, sxxh, sxyh, syyh, sqxh, sqyh, s1h, s2h, s3h, s4h, ob, pix0 + 128);
    }
    {   // set B -> pixels pix0+256, pix0+384
        float swl, swh, sxl, sxh, syl, syh, sxxl, sxxh, sxyl, sxyh, syyl, syyh;
        float sqxl, sqxh, sqyl, sqyh, s1l, s1h, s2l, s2h, s3l, s3h, s4l, s4h;
        f2unpack(swB, swl, swh);   f2unpack(SxB, sxl, sxh);   f2unpack(SyB, syl, syh);
        f2unpack(SxxB, sxxl, sxxh); f2unpack(SxyB, sxyl, sxyh); f2unpack(SyyB, syyl, syyh);
        f2unpack(SqxB, sqxl, sqxh); f2unpack(SqyB, sqyl, sqyh);
        f2unpack(S1B, s1l, s1h); f2unpack(S2B, s2l, s2h);
        f2unpack(S3B, s3l, s3h); f2unpack(S4B, s4l, s4h);
        mls_finish(swl, sxl, syl, sxxl, sxyl, syyl, sqxl, sqyl, s1l, s2l, s3l, s4l, ob, pix0 + 256);
        mls_finish(swh, sxh, syh, sxxh, sxyh, syyh, sqxh, sqyh, s1h, s2h, s3h, s4h, ob, pix0 + 384);
    }
}

extern "C" void kernel_launch(void* const* d_in, const int* in_sizes, int n_in,
                              void* d_out, int out_size)
{
    const float* sp = (const float*)d_in[0];   // (B, 68, 2)
    const float* dp = (const float*)d_in[1];   // (B, 68, 2)
    float* out = (float*)d_out;                // (B, 2, 32, 32)

    int B = in_sizes[0] / (NCTRL * 2);         // 512 for this problem
    dim3 grid(2, B);
    mls_warp_kernel<<<grid, 128>>>(sp, dp, out);
}

// round 15
// speedup vs baseline: 1.3001x; 1.3001x over previous
#include <cuda_runtime.h>
#include <cuda_bf16.h>

#define GSZ   32
#define NCTRL 68

typedef unsigned long long u64;

__device__ __forceinline__ u64 f2pack(float lo, float hi) {
    u64 r; asm("mov.b64 %0,{%1,%2};" : "=l"(r) : "f"(lo), "f"(hi)); return r;
}
__device__ __forceinline__ void f2unpack(u64 v, float& lo, float& hi) {
    asm("mov.b64 {%0,%1},%2;" : "=f"(lo), "=f"(hi) : "l"(v));
}
__device__ __forceinline__ float frcp(float x) {
    float r; asm("rcp.approx.f32 %0,%1;" : "=f"(r) : "f"(x)); return r;
}

// Weights for the thread's FOUR pixels, entirely off the fma pipe:
// integer d^2 (alu IADD/IMAD, exact), cvt to f32 (exact for d2<=1922),
// max(f,1e-8) (FMNMX on alu) reproduces reference d2+eps semantics
// (d2>=1: +1e-8 is below 1/2 ulp; d2==0 -> 1e-8 -> w=1e8), then MUFU rcp.
__device__ __forceinline__ void mls_weights(
    u64& wA, u64& wB, unsigned s, int col, int r0)
{
    asm("{\n\t"
        ".reg .u32 kxi, kyi;\n\t"
        ".reg .s32 dx, dy0, dy1, dy2, dy3, dx2, d0, d1, d2, d3;\n\t"
        ".reg .f32 f0, f1, f2, f3;\n\t"
        "ld.shared.v2.u32 {kxi, kyi}, [%2+32];\n\t"
        "sub.s32 dx, kxi, %3;\n\t"
        "sub.s32 dy0, kyi, %4;\n\t"
        "mul.lo.s32 dx2, dx, dx;\n\t"
        "sub.s32 dy1, dy0, 4;\n\t"
        "sub.s32 dy2, dy0, 8;\n\t"
        "sub.s32 dy3, dy0, 12;\n\t"
        "mad.lo.s32 d0, dy0, dy0, dx2;\n\t"
        "mad.lo.s32 d1, dy1, dy1, dx2;\n\t"
        "mad.lo.s32 d2, dy2, dy2, dx2;\n\t"
        "mad.lo.s32 d3, dy3, dy3, dx2;\n\t"
        "cvt.rn.f32.s32 f0, d0;\n\t"
        "cvt.rn.f32.s32 f1, d1;\n\t"
        "cvt.rn.f32.s32 f2, d2;\n\t"
        "cvt.rn.f32.s32 f3, d3;\n\t"
        "max.f32 f0, f0, 0f322BCC77;\n\t"
        "max.f32 f1, f1, 0f322BCC77;\n\t"
        "max.f32 f2, f2, 0f322BCC77;\n\t"
        "max.f32 f3, f3, 0f322BCC77;\n\t"
        "rcp.approx.f32 f0, f0;\n\t"
        "rcp.approx.f32 f1, f1;\n\t"
        "rcp.approx.f32 f2, f2;\n\t"
        "rcp.approx.f32 f3, f3;\n\t"
        "mov.b64 %0, {f0, f1};\n\t"
        "mov.b64 %1, {f2, f3};\n\t"
        "}"
        : "=l"(wA), "=l"(wB)
        : "r"(s), "r"(col), "r"(r0));
}

// Pure f32x2 math, 31 fma-pipe ops: dx, dyA, dyB(=dyA-8), 4 muls, 24 accums.
__device__ __forceinline__ void mls_accum(
    u64& swA, u64& SxA, u64& SyA, u64& SxxA, u64& SxyA, u64& SyyA,
    u64& SqxA, u64& SqyA, u64& S1A, u64& S2A, u64& S3A, u64& S4A,
    u64& swB, u64& SxB, u64& SyB, u64& SxxB, u64& SxyB, u64& SyyB,
    u64& SqxB, u64& SqyB, u64& S1B, u64& S2B, u64& S3B, u64& S4B,
    u64 wA, u64 wB, unsigned s, u64 nvx2, u64 nvyA2, u64 m8)
{
    asm("{\n\t"
        ".reg .b64 kx2, ky2, qx2, qy2, dx, dyA, dyB;\n\t"
        ".reg .b64 wdxA, wdyA, wdxB, wdyB;\n\t"
        "ld.shared.v2.b64 {kx2, ky2}, [%26];\n\t"
        "ld.shared.v2.b64 {qx2, qy2}, [%26+16];\n\t"
        "add.rn.f32x2 dx, kx2, %27;\n\t"
        "add.rn.f32x2 dyA, ky2, %28;\n\t"
        "add.rn.f32x2 dyB, dyA, %29;\n\t"
        "mul.rn.f32x2 wdxA, %24, dx;\n\t"
        "mul.rn.f32x2 wdyA, %24, dyA;\n\t"
        "mul.rn.f32x2 wdxB, %25, dx;\n\t"
        "mul.rn.f32x2 wdyB, %25, dyB;\n\t"
        // set A accumulators
        "add.rn.f32x2 %0, %0, %24;\n\t"
        "add.rn.f32x2 %1, %1, wdxA;\n\t"
        "add.rn.f32x2 %2, %2, wdyA;\n\t"
        "fma.rn.f32x2 %3, wdxA, dx, %3;\n\t"
        "fma.rn.f32x2 %4, wdxA, dyA, %4;\n\t"
        "fma.rn.f32x2 %5, wdyA, dyA, %5;\n\t"
        "fma.rn.f32x2 %6, %24, qx2, %6;\n\t"
        "fma.rn.f32x2 %7, %24, qy2, %7;\n\t"
        "fma.rn.f32x2 %8, wdxA, qx2, %8;\n\t"
        "fma.rn.f32x2 %9, wdyA, qx2, %9;\n\t"
        "fma.rn.f32x2 %10, wdxA, qy2, %10;\n\t"
        "fma.rn.f32x2 %11, wdyA, qy2, %11;\n\t"
        // set B accumulators
        "add.rn.f32x2 %12, %12, %25;\n\t"
        "add.rn.f32x2 %13, %13, wdxB;\n\t"
        "add.rn.f32x2 %14, %14, wdyB;\n\t"
        "fma.rn.f32x2 %15, wdxB, dx, %15;\n\t"
        "fma.rn.f32x2 %16, wdxB, dyB, %16;\n\t"
        "fma.rn.f32x2 %17, wdyB, dyB, %17;\n\t"
        "fma.rn.f32x2 %18, %25, qx2, %18;\n\t"
        "fma.rn.f32x2 %19, %25, qy2, %19;\n\t"
        "fma.rn.f32x2 %20, wdxB, qx2, %20;\n\t"
        "fma.rn.f32x2 %21, wdyB, qx2, %21;\n\t"
        "fma.rn.f32x2 %22, wdxB, qy2, %22;\n\t"
        "fma.rn.f32x2 %23, wdyB, qy2, %23;\n\t"
        "}"
        : "+l"(swA), "+l"(SxA), "+l"(SyA), "+l"(SxxA), "+l"(SxyA), "+l"(SyyA),
          "+l"(SqxA), "+l"(SqyA), "+l"(S1A), "+l"(S2A), "+l"(S3A), "+l"(S4A),
          "+l"(swB), "+l"(SxB), "+l"(SyB), "+l"(SxxB), "+l"(SxyB), "+l"(SyyB),
          "+l"(SqxB), "+l"(SqyB), "+l"(S1B), "+l"(S2B), "+l"(S3B), "+l"(S4B)
        : "l"(wA), "l"(wB), "r"(s), "l"(nvx2), "l"(nvyA2), "l"(m8));
}

// Scalar epilogue: closed-form 2x2 solve from raw weighted moments.
__device__ __forceinline__ void mls_finish(
    float sw, float sx, float sy,
    float sxx, float sxy, float syy,
    float sqx, float sqy,
    float sdxqx, float sdyqx, float sdxqy, float sdyqy,
    float* __restrict__ ob, int pix)
{
    const float isw = frcp(sw);
    const float mx  = sx * isw,  my  = sy * isw;
    const float a11 = fmaf(sxx, isw, -(mx * mx));
    const float a12 = fmaf(sxy, isw, -(mx * my));
    const float a22 = fmaf(syy, isw, -(my * my));
    const float qsx = sqx * isw, qsy = sqy * isw;
    const float bxx = fmaf(sdxqx, isw, -(mx * qsx));
    const float bxy = fmaf(sdyqx, isw, -(my * qsx));
    const float byx = fmaf(sdxqy, isw, -(mx * qsy));
    const float byy = fmaf(sdyqy, isw, -(my * qsy));

    const float det  = fmaf(a11, a22, -(a12 * a12));
    const float idet = frcp(det);
    const float ux = -mx, uy = -my;
    const float rx = (ux * a22 - uy * a12) * idet;
    const float ry = (uy * a11 - ux * a12) * idet;

    float tx = fmaf(rx, bxx, fmaf(ry, bxy, qsx));
    float ty = fmaf(rx, byx, fmaf(ry, byy, qsy));

    if (!(tx >= 0.f) || tx > (float)(GSZ - 1)) tx = 0.f;
    if (!(ty >= 0.f) || ty > (float)(GSZ - 1)) ty = 0.f;

    ob[pix]             = tx;   // channel 0 (x)
    ob[GSZ * GSZ + pix] = ty;   // channel 1 (y)
}

// 128 threads per CTA, each handles 4 pixels in one column: rows r0, r0+4,
// r0+8, r0+12 of a 16-row band. grid = (2, B).
__global__ __launch_bounds__(128)
void mls_warp_kernel(const float* __restrict__ sp,
                     const float* __restrict__ dp,
                     float* __restrict__ out)
{
    // Per control, 48B: kx2(8) ky2(8) qx2(8) qy2(8) kxi(4) kyi(4) pad(8)
    __shared__ __align__(16) u64 cs[NCTRL * 6];

    const int b    = blockIdx.y;
    const int band = blockIdx.x;
    const int tid  = threadIdx.x;

    if (tid < NCTRL) {
        const float* spb = sp + (size_t)b * (NCTRL * 2) + tid * 2;
        const float* dpb = dp + (size_t)b * (NCTRL * 2) + tid * 2;
        // coord swap + int16 truncation, exactly as the reference
        int   kxi = (int)(short)dpb[1];
        int   kyi = (int)(short)dpb[0];
        float kx = (float)kxi, ky = (float)kyi;
        float qx = (float)(short)spb[1];
        float qy = (float)(short)spb[0];
        cs[tid * 6 + 0] = f2pack(kx, kx);
        cs[tid * 6 + 1] = f2pack(ky, ky);
        cs[tid * 6 + 2] = f2pack(qx, qx);
        cs[tid * 6 + 3] = f2pack(qy, qy);
        ((int*)&cs[tid * 6 + 4])[0] = kxi;
        ((int*)&cs[tid * 6 + 4])[1] = kyi;
    }
    __syncthreads();

    const int pix0 = band * 512 + tid;         // pixels at pix0 + {0,128,256,384}
    const int col  = tid & 31;
    const int r0   = band * 16 + (tid >> 5);
    const float vx = (float)col;
    const float fr0 = (float)r0;

    const u64 nvx2  = f2pack(-vx, -vx);
    const u64 nvyA2 = f2pack(-fr0, -(fr0 + 4.0f));   // rows r0, r0+4
    const u64 m8    = f2pack(-8.0f, -8.0f);          // dyB = dyA - 8

    u64 swA = 0, SxA = 0, SyA = 0, SxxA = 0, SxyA = 0, SyyA = 0;
    u64 SqxA = 0, SqyA = 0, S1A = 0, S2A = 0, S3A = 0, S4A = 0;
    u64 swB = 0, SxB = 0, SyB = 0, SxxB = 0, SxyB = 0, SyyB = 0;
    u64 SqxB = 0, SqyB = 0, S1B = 0, S2B = 0, S3B = 0, S4B = 0;

    unsigned s = (unsigned)__cvta_generic_to_shared(cs);
#pragma unroll 2
    for (int c = 0; c < NCTRL; ++c, s += 48u) {
        u64 wA, wB;
        mls_weights(wA, wB, s, col, r0);
        mls_accum(swA, SxA, SyA, SxxA, SxyA, SyyA, SqxA, SqyA, S1A, S2A, S3A, S4A,
                  swB, SxB, SyB, SxxB, SxyB, SyyB, SqxB, SqyB, S1B, S2B, S3B, S4B,
                  wA, wB, s, nvx2, nvyA2, m8);
    }

    float* ob = out + (size_t)b * (2 * GSZ * GSZ);

    {   // set A -> pixels pix0, pix0+128
        float swl, swh, sxl, sxh, syl, syh, sxxl, sxxh, sxyl, sxyh, syyl, syyh;
        float sqxl, sqxh, sqyl, sqyh, s1l, s1h, s2l, s2h, s3l, s3h, s4l, s4h;
        f2unpack(swA, swl, swh);   f2unpack(SxA, sxl, sxh);   f2unpack(SyA, syl, syh);
        f2unpack(SxxA, sxxl, sxxh); f2unpack(SxyA, sxyl, sxyh); f2unpack(SyyA, syyl, syyh);
        f2unpack(SqxA, sqxl, sqxh); f2unpack(SqyA, sqyl, sqyh);
        f2unpack(S1A, s1l, s1h); f2unpack(S2A, s2l, s2h);
        f2unpack(S3A, s3l, s3h); f2unpack(S4A, s4l, s4h);
        mls_finish(swl, sxl, syl, sxxl, sxyl, syyl, sqxl, sqyl, s1l, s2l, s3l, s4l, ob, pix0);
        mls_finish(swh, sxh, syh, sxxh, sxyh, syyh, sqxh, sqyh, s1h, s2h, s3h, s4h, ob, pix0 + 128);
    }
    {   // set B -> pixels pix0+256, pix0+384
        float swl, swh, sxl, sxh, syl, syh, sxxl, sxxh, sxyl, sxyh, syyl, syyh;
        float sqxl, sqxh, sqyl, sqyh, s1l, s1h, s2l, s2h, s3l, s3h, s4l, s4h;
        f2unpack(swB, swl, swh);   f2unpack(SxB, sxl, sxh);   f2unpack(SyB, syl, syh);
        f2unpack(SxxB, sxxl, sxxh); f2unpack(SxyB, sxyl, sxyh); f2unpack(SyyB, syyl, syyh);
        f2unpack(SqxB, sqxl, sqxh); f2unpack(SqyB, sqyl, sqyh);
        f2unpack(S1B, s1l, s1h); f2unpack(S2B, s2l, s2h);
        f2unpack(S3B, s3l, s3h); f2unpack(S4B, s4l, s4h);
        mls_finish(swl, sxl, syl, sxxl, sxyl, syyl, sqxl, sqyl, s1l, s2l, s3l, s4l, ob, pix0 + 256);
        mls_finish(swh, sxh, syh, sxxh, sxyh, syyh, sqxh, sqyh, s1h, s2h, s3h, s4h, ob, pix0 + 384);
    }
}

extern "C" void kernel_launch(void* const* d_in, const int* in_sizes, int n_in,
                              void* d_out, int out_size)
{
    const float* sp = (const float*)d_in[0];   // (B, 68, 2)
    const float* dp = (const float*)d_in[1];   // (B, 68, 2)
    float* out = (float*)d_out;                // (B, 2, 32, 32)

    int B = in_sizes[0] / (NCTRL * 2);         // 512 for this problem
    dim3 grid(2, B);
    mls_warp_kernel<<<grid, 128>>>(sp, dp, out);
}